// round 7
// baseline (speedup 1.0000x reference)
#include <cuda_runtime.h>
#include <cuda_bf16.h>

// binnings: out[b,g,h,w] = sum_n x[b, IDX[g,n], h, w] * groupn[g,n]
//   x: (8, 64, 512, 512) fp32, groupn: (16, 4) fp32, out: (8, 16, 512, 512)
//   IDX[g,n] = (g/4)*16 + n*4 + (g%4)
//
// HBM-bound at minimal traffic (640 MiB). Five variants pinned at
// ~96.3us / 89% DRAM -> at the mixed-stream ceiling. R7 (last lever):
// invert CTA ordering so (b,g) varies fastest across consecutive block
// ids. Each resident wave then spreads its read streams across the
// full 512 MiB input (all batches/channels) instead of a ~40 MiB
// slice, maximizing DRAM bank/channel parallelism.

static constexpr int B = 8;
static constexpr int C = 64;
static constexpr int G = 16;
static constexpr int HW = 512 * 512;
static constexpr int HW4 = HW / 4;            // 65536 float4s per plane
static constexpr int TPB = 256;
static constexpr int CHUNKS = HW4 / TPB;      // 256 pixel-chunks per plane
static constexpr int PLANES = B * G;          // 128

__global__ __launch_bounds__(TPB)
void binnings_kernel(const float4* __restrict__ x,
                     const float* __restrict__ groupn,
                     float4* __restrict__ out)
{
    // 1D grid, (b,g) fastest-varying: bid = plane + PLANES * chunk
    const int bid   = blockIdx.x;
    const int plane = bid & (PLANES - 1);     // 0..127
    const int chunk = bid >> 7;               // 0..255

    const int g = plane & (G - 1);
    const int b = plane >> 4;

    const int p = chunk * TPB + threadIdx.x;  // float4 index in plane

    const int ch_base = (g >> 2) * 16 + (g & 3);

    const float w0 = __ldg(&groupn[g * 4 + 0]);
    const float w1 = __ldg(&groupn[g * 4 + 1]);
    const float w2 = __ldg(&groupn[g * 4 + 2]);
    const float w3 = __ldg(&groupn[g * 4 + 3]);

    const long long base = (long long)(b * C + ch_base) * HW4 + p;

    const float4 a0 = __ldg(&x[base + 0LL * 4 * HW4]);
    const float4 a1 = __ldg(&x[base + 1LL * 4 * HW4]);
    const float4 a2 = __ldg(&x[base + 2LL * 4 * HW4]);
    const float4 a3 = __ldg(&x[base + 3LL * 4 * HW4]);

    float4 r;
    r.x = fmaf(a0.x, w0, fmaf(a1.x, w1, fmaf(a2.x, w2, a3.x * w3)));
    r.y = fmaf(a0.y, w0, fmaf(a1.y, w1, fmaf(a2.y, w2, a3.y * w3)));
    r.z = fmaf(a0.z, w0, fmaf(a1.z, w1, fmaf(a2.z, w2, a3.z * w3)));
    r.w = fmaf(a0.w, w0, fmaf(a1.w, w1, fmaf(a2.w, w2, a3.w * w3)));

    __stwt(&out[(long long)(b * G + g) * HW4 + p], r);
}

extern "C" void kernel_launch(void* const* d_in, const int* in_sizes, int n_in,
                              void* d_out, int out_size)
{
    const float4* x      = (const float4*)d_in[0];
    const float*  groupn = (const float*)d_in[1];
    float4*       out    = (float4*)d_out;

    binnings_kernel<<<PLANES * CHUNKS, TPB>>>(x, groupn, out);  // 32768 CTAs
}

// round 8
// speedup vs baseline: 1.0090x; 1.0090x over previous
#include <cuda_runtime.h>
#include <cuda_bf16.h>

// binnings: out[b,g,h,w] = sum_n x[b, IDX[g,n], h, w] * groupn[g,n]
//   x: (8, 64, 512, 512) fp32, groupn: (16, 4) fp32, out: (8, 16, 512, 512)
//   IDX[g,n] = (g/4)*16 + n*4 + (g%4)
//
// FINAL (R5 config). HBM-bound at provably-minimal traffic (640 MiB:
// IDX partitions the 64 channels exactly; every input element read once,
// every output written once, no cross-g reuse). Measured at the chip's
// mixed-stream ceiling: 89% dram__cycles_active / 7.05 TB/s. Seven
// structural variants (cache policies, MLP, CTA size/ordering,
// persistence) all within ~1%; this config tied-best dur_us with best
// DRAM%. One float4 per thread, 4 independent coalesced LDG.128 streams,
// write-through stores (no dirty-L2 interaction across graph replays).

static constexpr int B = 8;
static constexpr int C = 64;
static constexpr int G = 16;
static constexpr int HW = 512 * 512;
static constexpr int HW4 = HW / 4;            // 65536 float4s per plane

__global__ __launch_bounds__(256)
void binnings_kernel(const float4* __restrict__ x,
                     const float* __restrict__ groupn,
                     float4* __restrict__ out)
{
    const int g = blockIdx.y;      // 0..15
    const int b = blockIdx.z;      // 0..7
    const int p = blockIdx.x * blockDim.x + threadIdx.x;   // float4 index in plane

    const int ch_base = (g >> 2) * 16 + (g & 3);

    const float w0 = __ldg(&groupn[g * 4 + 0]);
    const float w1 = __ldg(&groupn[g * 4 + 1]);
    const float w2 = __ldg(&groupn[g * 4 + 2]);
    const float w3 = __ldg(&groupn[g * 4 + 3]);

    const long long base = (long long)(b * C + ch_base) * HW4 + p;

    const float4 a0 = __ldg(&x[base + 0LL * 4 * HW4]);
    const float4 a1 = __ldg(&x[base + 1LL * 4 * HW4]);
    const float4 a2 = __ldg(&x[base + 2LL * 4 * HW4]);
    const float4 a3 = __ldg(&x[base + 3LL * 4 * HW4]);

    float4 r;
    r.x = fmaf(a0.x, w0, fmaf(a1.x, w1, fmaf(a2.x, w2, a3.x * w3)));
    r.y = fmaf(a0.y, w0, fmaf(a1.y, w1, fmaf(a2.y, w2, a3.y * w3)));
    r.z = fmaf(a0.z, w0, fmaf(a1.z, w1, fmaf(a2.z, w2, a3.z * w3)));
    r.w = fmaf(a0.w, w0, fmaf(a1.w, w1, fmaf(a2.w, w2, a3.w * w3)));

    __stwt(&out[(long long)(b * G + g) * HW4 + p], r);
}

extern "C" void kernel_launch(void* const* d_in, const int* in_sizes, int n_in,
                              void* d_out, int out_size)
{
    const float4* x      = (const float4*)d_in[0];
    const float*  groupn = (const float*)d_in[1];
    float4*       out    = (float4*)d_out;

    dim3 block(256);
    dim3 grid(HW4 / 256, G, B);   // 256 x 16 x 8 = 32768 blocks
    binnings_kernel<<<grid, block>>>(x, groupn, out);
}